// round 5
// baseline (speedup 1.0000x reference)
#include <cuda_runtime.h>
#include <cuda_bf16.h>
#include <cstdint>
#include <math.h>

#define DIN 768
#define H   256
#define NH  4
#define HD  64

#define BM   128
#define BN   256         // full H kept in-CTA for fused epilogue
#define BK   32
#define NKC  (DIN / BK)  // 24 k-chunks
#define NTH  512
#define ASTR 36          // fp32 smem stride for A (144B rows, 16B-aligned)
#define BSTR 40          // bf16 smem stride for B (80B rows, 16B-aligned)
#define SL_STR 257       // epilogue row stride

#define A_BYTES (BM * ASTR * 4)          // 18432 per buffer
#define B_BYTES (BN * BSTR * 2)          // 20480 per buffer per split
#define BH_OFF  (2 * A_BYTES)            // 36864
#define BL_OFF  (BH_OFF + 2 * B_BYTES)   // 77824
#define SMEM_BYTES (BM * SL_STR * 4)     // 131584 (epilogue region is the max)

// ---- folded prep outputs ----
__device__ float g_wfold[NH][H];
__device__ float g_cfold[NH];
__device__ float g_base[H];
__device__ float g_colf[NH][H];
// ---- prepacked Wl hi/lo bf16 (loop-invariant; device-global scratch) ----
__device__ unsigned short g_WlHi[H * DIN];
__device__ unsigned short g_WlLo[H * DIN];

// =====================================================================
// Prep: all O(1)-in-M math. 1 CTA x 256 threads.
// =====================================================================
__global__ void prep_kernel(const float* __restrict__ user,
                            const float* __restrict__ query,
                            const float* __restrict__ Wu, const float* __restrict__ bu,
                            const float* __restrict__ Wq, const float* __restrict__ bq,
                            const float* __restrict__ inw, const float* __restrict__ inb,
                            const float* __restrict__ ow,  const float* __restrict__ ob)
{
    __shared__ float su[H], sq[H], k0[H], k1[H], v0[H], v1[H];
    const int t = threadIdx.x;

    float au = bu[t], aq = bq[t];
    for (int j = 0; j < DIN; j++) {
        au = fmaf(Wu[t * DIN + j], user[j],  au);
        aq = fmaf(Wq[t * DIN + j], query[j], aq);
    }
    su[t] = au; sq[t] = aq;
    __syncthreads();

    float k0a = inb[H + t], k1a = inb[H + t];
    float v0a = inb[2 * H + t], v1a = inb[2 * H + t];
    for (int j = 0; j < H; j++) {
        float wk = inw[(H + t) * H + j];
        float wv = inw[(2 * H + t) * H + j];
        k0a = fmaf(wk, su[j], k0a);  k1a = fmaf(wk, sq[j], k1a);
        v0a = fmaf(wv, su[j], v0a);  v1a = fmaf(wv, sq[j], v1a);
    }
    k0[t] = k0a; k1[t] = k1a; v0[t] = v0a; v1[t] = v1a;
    __syncthreads();

    const float scale = rsqrtf((float)HD);
    #pragma unroll
    for (int h = 0; h < NH; h++) {
        float acc = 0.f;
        for (int d = 0; d < HD; d++) {
            float dk = (k0[h * HD + d] - k1[h * HD + d]) * scale;
            acc = fmaf(dk, inw[(h * HD + d) * H + t], acc);
        }
        g_wfold[h][t] = acc;
    }
    if (t < NH) {
        float acc = 0.f;
        for (int d = 0; d < HD; d++)
            acc = fmaf((k0[t * HD + d] - k1[t * HD + d]) * scale, inb[t * HD + d], acc);
        g_cfold[t] = acc;
    }

    float accb = ob[t];
    for (int j = 0; j < H; j++) accb = fmaf(ow[t * H + j], v1[j], accb);
    g_base[t] = accb;
    #pragma unroll
    for (int h = 0; h < NH; h++) {
        float acc = 0.f;
        for (int d = 0; d < HD; d++)
            acc = fmaf(ow[t * H + h * HD + d], v0[h * HD + d] - v1[h * HD + d], acc);
        g_colf[h][t] = acc;
    }
}

// =====================================================================
// Prepack: Wl -> (hi, lo) bf16 split, once per launch.
// hi = truncate-to-bf16(f); lo = truncate-to-bf16(f - hi)  (residual exact)
// =====================================================================
__global__ void prepack_kernel(const float* __restrict__ Wl)
{
    int i = blockIdx.x * blockDim.x + threadIdx.x;
    if (i < H * DIN) {
        uint32_t u  = __float_as_uint(Wl[i]);
        uint32_t hi = u & 0xFFFF0000u;
        float r = __uint_as_float(u) - __uint_as_float(hi);
        g_WlHi[i] = (unsigned short)(hi >> 16);
        g_WlLo[i] = (unsigned short)(__float_as_uint(r) >> 16);
    }
}

// ---------------- helpers ----------------
__device__ __forceinline__ uint32_t smem_u32(const void* p) {
    uint32_t a;
    asm("{ .reg .u64 t; cvta.to.shared.u64 t, %1; cvt.u32.u64 %0, t; }" : "=r"(a) : "l"(p));
    return a;
}
__device__ __forceinline__ void cp16(uint32_t dst, const void* src) {
    asm volatile("cp.async.cg.shared.global [%0], [%1], 16;" :: "r"(dst), "l"(src));
}
__device__ __forceinline__ void cp_commit() { asm volatile("cp.async.commit_group;"); }
template <int N> __device__ __forceinline__ void cp_wait() {
    asm volatile("cp.async.wait_group %0;" :: "n"(N));
}
// bf16x2 hi pack (truncation) of float2
__device__ __forceinline__ uint32_t pack_hi(float2 f) {
    return __byte_perm(__float_as_uint(f.x), __float_as_uint(f.y), 0x7632);
}
// bf16x2 lo pack: exact residual of truncation, then truncate-pack
__device__ __forceinline__ uint32_t pack_lo(float2 f) {
    float hx = __uint_as_float(__float_as_uint(f.x) & 0xFFFF0000u);
    float hy = __uint_as_float(__float_as_uint(f.y) & 0xFFFF0000u);
    return __byte_perm(__float_as_uint(f.x - hx), __float_as_uint(f.y - hy), 0x7632);
}
__device__ __forceinline__ void mma16816(float* d, uint32_t a0, uint32_t a1,
                                         uint32_t a2, uint32_t a3,
                                         uint32_t b0, uint32_t b1) {
    asm volatile(
        "mma.sync.aligned.m16n8k16.row.col.f32.bf16.bf16.f32 "
        "{%0,%1,%2,%3}, {%4,%5,%6,%7}, {%8,%9}, {%0,%1,%2,%3};"
        : "+f"(d[0]), "+f"(d[1]), "+f"(d[2]), "+f"(d[3])
        : "r"(a0), "r"(a1), "r"(a2), "r"(a3), "r"(b0), "r"(b1));
}

// =====================================================================
// Main: 128x256 tile of l = X@Wl^T + bl via mma.sync bf16 3-term split.
// A staged fp32 + split in-loop; B pre-split (g_WlHi/g_WlLo) staged bf16.
// cp.async double-buffered; fused folded-attention epilogue.
// 16 warps: warp_m = wid&3 (32 rows), warp_n = wid>>2 (64 cols).
// =====================================================================
__global__ __launch_bounds__(NTH, 1)
void main_kernel(const float* __restrict__ X,  const float* __restrict__ bl,
                 const float* __restrict__ Wo, const float* __restrict__ bo,
                 float* __restrict__ out, int M)
{
    extern __shared__ char smc[];
    float* smf = (float*)smc;
    const uint32_t sb = smem_u32(smc);
    const int t    = threadIdx.x;
    const int wid  = t >> 5;
    const int lane = t & 31;
    const int q    = lane & 3;       // pair-of-k selector
    const int g8   = lane >> 2;      // 0..7 row/col within 8-group
    const int wm   = wid & 3;        // 0..3 -> 32-row slab
    const int wn   = wid >> 2;       // 0..3 -> 64-col slab
    const size_t row0 = (size_t)blockIdx.x * BM;

    // accumulators [mt][nt][4], seeded with bl so acc == l at the end
    float acc[2][8][4];
    #pragma unroll
    for (int nt = 0; nt < 8; nt++) {
        int c0 = wn * 64 + nt * 8 + 2 * q;
        float b0 = __ldg(bl + c0), b1 = __ldg(bl + c0 + 1);
        #pragma unroll
        for (int mt = 0; mt < 2; mt++) {
            acc[mt][nt][0] = b0; acc[mt][nt][1] = b1;
            acc[mt][nt][2] = b0; acc[mt][nt][3] = b1;
        }
    }

    // ---- cp.async tile loaders ----
    auto load_tiles = [&](int c, int buf) {
        // A: 128 rows x 32 fp32 = 1024 x 16B chunks -> 2/thread
        #pragma unroll
        for (int i = 0; i < 2; i++) {
            int id = t + NTH * i;
            int r = id >> 3, cq = id & 7;
            size_t gr = row0 + r; if (gr >= (size_t)M) gr = (size_t)M - 1;
            uint32_t dst = sb + (uint32_t)(buf * A_BYTES + (r * ASTR + cq * 4) * 4);
            cp16(dst, X + gr * DIN + c * BK + cq * 4);
        }
        // B hi/lo: 256 rows x 32 bf16 = 1024 x 16B chunks each -> 2+2/thread
        #pragma unroll
        for (int i = 0; i < 2; i++) {
            int id = t + NTH * i;
            int r = id >> 2, cq = id & 3;
            size_t srco = (size_t)r * DIN + c * BK + cq * 8;
            uint32_t doff = (uint32_t)(buf * B_BYTES + (r * BSTR + cq * 8) * 2);
            cp16(sb + BH_OFF + doff, g_WlHi + srco);
            cp16(sb + BL_OFF + doff, g_WlLo + srco);
        }
    };

    load_tiles(0, 0);
    cp_commit();

    const int ra_base = wm * 32;
    const int nb_base = wn * 64;

    for (int c = 0; c < NKC; c++) {
        if (c + 1 < NKC) { load_tiles(c + 1, (c + 1) & 1); cp_commit(); cp_wait<1>(); }
        else            { cp_wait<0>(); }
        __syncthreads();

        const float* smA = (const float*)(smc + (c & 1) * A_BYTES);
        const char*  sBh = smc + BH_OFF + (c & 1) * B_BYTES;
        const char*  sBl = smc + BL_OFF + (c & 1) * B_BYTES;

        #pragma unroll
        for (int ks = 0; ks < 2; ks++) {
            const int kk = ks * 16 + 2 * q;
            // A fragments (hi+lo) for both 16-row m-tiles
            uint32_t Ah[2][4], Al[2][4];
            #pragma unroll
            for (int mt = 0; mt < 2; mt++) {
                int ra = ra_base + mt * 16 + g8;
                float2 f0 = *(const float2*)&smA[ ra      * ASTR + kk    ];
                float2 f1 = *(const float2*)&smA[(ra + 8) * ASTR + kk    ];
                float2 f2 = *(const float2*)&smA[ ra      * ASTR + kk + 8];
                float2 f3 = *(const float2*)&smA[(ra + 8) * ASTR + kk + 8];
                Ah[mt][0] = pack_hi(f0); Ah[mt][1] = pack_hi(f1);
                Ah[mt][2] = pack_hi(f2); Ah[mt][3] = pack_hi(f3);
                Al[mt][0] = pack_lo(f0); Al[mt][1] = pack_lo(f1);
                Al[mt][2] = pack_lo(f2); Al[mt][3] = pack_lo(f3);
            }
            #pragma unroll
            for (int nt = 0; nt < 8; nt++) {
                int nb = nb_base + nt * 8 + g8;
                uint32_t bh0 = *(const uint32_t*)(sBh + (nb * BSTR + kk) * 2);
                uint32_t bh1 = *(const uint32_t*)(sBh + (nb * BSTR + kk + 8) * 2);
                uint32_t bL0 = *(const uint32_t*)(sBl + (nb * BSTR + kk) * 2);
                uint32_t bL1 = *(const uint32_t*)(sBl + (nb * BSTR + kk + 8) * 2);
                #pragma unroll
                for (int mt = 0; mt < 2; mt++) {
                    mma16816(acc[mt][nt], Ah[mt][0], Ah[mt][1], Ah[mt][2], Ah[mt][3], bh0, bh1);
                    mma16816(acc[mt][nt], Al[mt][0], Al[mt][1], Al[mt][2], Al[mt][3], bh0, bh1);
                    mma16816(acc[mt][nt], Ah[mt][0], Ah[mt][1], Ah[mt][2], Ah[mt][3], bL0, bL1);
                }
            }
        }
        __syncthreads();
    }

    // ---------------- stage l to smem (reuses pipeline region) ----------------
    float* s_l = smf;
    #pragma unroll
    for (int mt = 0; mt < 2; mt++) {
        int r = wm * 32 + mt * 16 + g8;
        #pragma unroll
        for (int nt = 0; nt < 8; nt++) {
            int cc = wn * 64 + nt * 8 + 2 * q;
            s_l[ r      * SL_STR + cc    ] = acc[mt][nt][0];
            s_l[ r      * SL_STR + cc + 1] = acc[mt][nt][1];
            s_l[(r + 8) * SL_STR + cc    ] = acc[mt][nt][2];
            s_l[(r + 8) * SL_STR + cc + 1] = acc[mt][nt][3];
        }
    }
    __syncthreads();

    // ---------------- folded-attention epilogue ----------------
    // thread t: row = t>>2, part = t&3 owns cols [part*64, part*64+64)
    {
        const int row  = t >> 2;
        const int part = t & 3;
        const float* lrow = s_l + row * SL_STR;

        float s0 = 0.f, s1 = 0.f, s2 = 0.f, s3 = 0.f, pl = 0.f;
        #pragma unroll 4
        for (int j = 0; j < 64; j++) {
            int col = part * 64 + j;
            float lv = lrow[col];
            s0 = fmaf(g_wfold[0][col], lv, s0);
            s1 = fmaf(g_wfold[1][col], lv, s1);
            s2 = fmaf(g_wfold[2][col], lv, s2);
            s3 = fmaf(g_wfold[3][col], lv, s3);
            pl = fmaf(fmaxf(lv, 0.f), __ldg(Wo + H + col), pl);
        }
        #pragma unroll
        for (int off = 1; off <= 2; off <<= 1) {
            s0 += __shfl_xor_sync(0xffffffffu, s0, off);
            s1 += __shfl_xor_sync(0xffffffffu, s1, off);
            s2 += __shfl_xor_sync(0xffffffffu, s2, off);
            s3 += __shfl_xor_sync(0xffffffffu, s3, off);
        }
        float a00 = 1.f / (1.f + __expf(-(s0 + g_cfold[0])));
        float a01 = 1.f / (1.f + __expf(-(s1 + g_cfold[1])));
        float a02 = 1.f / (1.f + __expf(-(s2 + g_cfold[2])));
        float a03 = 1.f / (1.f + __expf(-(s3 + g_cfold[3])));

        float pat = 0.f;
        #pragma unroll 4
        for (int j = 0; j < 64; j++) {
            int col = part * 64 + j;
            float att = g_base[col];
            att = fmaf(a00, g_colf[0][col], att);
            att = fmaf(a01, g_colf[1][col], att);
            att = fmaf(a02, g_colf[2][col], att);
            att = fmaf(a03, g_colf[3][col], att);
            pat = fmaf(fmaxf(att, 0.f), __ldg(Wo + col), pat);
        }
        float tot = pat + pl;
        #pragma unroll
        for (int off = 1; off <= 2; off <<= 1)
            tot += __shfl_xor_sync(0xffffffffu, tot, off);

        size_t grow = row0 + row;
        if (part == 0 && grow < (size_t)M) out[grow] = tot + __ldg(bo);
    }
}

// =====================================================================
extern "C" void kernel_launch(void* const* d_in, const int* in_sizes, int n_in,
                              void* d_out, int out_size)
{
    const float* user  = (const float*)d_in[0];
    const float* query = (const float*)d_in[1];
    const float* llm   = (const float*)d_in[2];
    const float* Wu    = (const float*)d_in[3];
    const float* bu    = (const float*)d_in[4];
    const float* Wq    = (const float*)d_in[5];
    const float* bq    = (const float*)d_in[6];
    const float* Wl    = (const float*)d_in[7];
    const float* bl    = (const float*)d_in[8];
    const float* inw   = (const float*)d_in[9];
    const float* inb   = (const float*)d_in[10];
    const float* ow    = (const float*)d_in[11];
    const float* ob    = (const float*)d_in[12];
    const float* Wo    = (const float*)d_in[13];
    const float* bo    = (const float*)d_in[14];

    const int M = in_sizes[2] / DIN;

    cudaFuncSetAttribute(main_kernel, cudaFuncAttributeMaxDynamicSharedMemorySize, SMEM_BYTES);

    prep_kernel<<<1, 256>>>(user, query, Wu, bu, Wq, bq, inw, inb, ow, ob);
    prepack_kernel<<<(H * DIN + 511) / 512, 512>>>(Wl);
    main_kernel<<<(M + BM - 1) / BM, NTH, SMEM_BYTES>>>(llm, bl, Wo, bo, (float*)d_out, M);
}

// round 7
// speedup vs baseline: 1.4288x; 1.4288x over previous
#include <cuda_runtime.h>
#include <cuda_bf16.h>
#include <cstdint>
#include <math.h>

#define DIN 768
#define H   256
#define NH  4
#define HD  64

#define BM   128
#define BN   256         // full H kept in-CTA for fused epilogue
#define BK   32
#define NKC  (DIN / BK)  // 24 k-chunks
#define NTH  512
#define ASTR 36          // fp32 smem stride for A (144B rows, 16B-aligned)
#define BSTR 40          // bf16 smem stride for B (80B rows, 16B-aligned)
#define SL_STR 257       // epilogue row stride

#define A_BYTES (BM * ASTR * 4)          // 18432 per buffer
#define B_BYTES (BN * BSTR * 2)          // 20480 per buffer per split
#define BH_OFF  (2 * A_BYTES)            // 36864
#define BL_OFF  (BH_OFF + 2 * B_BYTES)   // 77824
#define SMEM_BYTES (BM * SL_STR * 4)     // 131584 (epilogue region is the max)

// ---- folded prep outputs ----
__device__ float g_wfold[NH][H];
__device__ float g_cfold[NH];
__device__ float g_base[H];
__device__ float g_colf[NH][H];
// ---- prep intermediates ----
__device__ float g_u[H], g_qv[H];
__device__ float g_k0[H], g_k1[H], g_v0[H], g_v1[H];
// ---- prepacked Wl hi/lo bf16 (loop-invariant; device-global scratch) ----
__device__ unsigned short g_WlHi[H * DIN];
__device__ unsigned short g_WlLo[H * DIN];

// =====================================================================
// P1: u = Wu@user+bu, qv = Wq@query+bq. 512 warp-dots of 768, coalesced.
// =====================================================================
__global__ void prep1_kernel(const float* __restrict__ user,
                             const float* __restrict__ query,
                             const float* __restrict__ Wu, const float* __restrict__ bu,
                             const float* __restrict__ Wq, const float* __restrict__ bq)
{
    const int w    = blockIdx.x * 8 + (threadIdx.x >> 5);   // 0..511
    const int lane = threadIdx.x & 31;
    const float* W = (w < H) ? (Wu + (size_t)w * DIN) : (Wq + (size_t)(w - H) * DIN);
    const float* x = (w < H) ? user : query;

    float s = 0.f;
    #pragma unroll
    for (int j = lane * 4; j < DIN; j += 128) {
        float4 f = *(const float4*)(W + j);
        float4 g = *(const float4*)(x + j);
        s += f.x * g.x + f.y * g.y + f.z * g.z + f.w * g.w;
    }
    #pragma unroll
    for (int o = 16; o >= 1; o >>= 1) s += __shfl_xor_sync(0xffffffffu, s, o);
    if (lane == 0) {
        if (w < H) g_u[w]      = s + bu[w];
        else       g_qv[w - H] = s + bq[w - H];
    }
}

// =====================================================================
// P2: k0,k1,v0,v1. 256 warps x 4 dots of 256, coalesced.
// =====================================================================
__global__ void prep2_kernel(const float* __restrict__ inw, const float* __restrict__ inb)
{
    const int w    = blockIdx.x * 8 + (threadIdx.x >> 5);   // 0..255
    const int lane = threadIdx.x & 31;
    const float* Wk = inw + (size_t)(H + w) * H;
    const float* Wv = inw + (size_t)(2 * H + w) * H;

    float k0 = 0.f, k1 = 0.f, v0 = 0.f, v1 = 0.f;
    #pragma unroll
    for (int j = lane * 4; j < H; j += 128) {
        float4 a  = *(const float4*)(Wk + j);
        float4 b  = *(const float4*)(Wv + j);
        float4 uu = *(const float4*)(g_u + j);
        float4 qq = *(const float4*)(g_qv + j);
        k0 += a.x * uu.x + a.y * uu.y + a.z * uu.z + a.w * uu.w;
        k1 += a.x * qq.x + a.y * qq.y + a.z * qq.z + a.w * qq.w;
        v0 += b.x * uu.x + b.y * uu.y + b.z * uu.z + b.w * uu.w;
        v1 += b.x * qq.x + b.y * qq.y + b.z * qq.z + b.w * qq.w;
    }
    #pragma unroll
    for (int o = 16; o >= 1; o >>= 1) {
        k0 += __shfl_xor_sync(0xffffffffu, k0, o);
        k1 += __shfl_xor_sync(0xffffffffu, k1, o);
        v0 += __shfl_xor_sync(0xffffffffu, v0, o);
        v1 += __shfl_xor_sync(0xffffffffu, v1, o);
    }
    if (lane == 0) {
        g_k0[w] = k0 + inb[H + w];
        g_k1[w] = k1 + inb[H + w];
        g_v0[w] = v0 + inb[2 * H + w];
        g_v1[w] = v1 + inb[2 * H + w];
    }
}

// =====================================================================
// P3: blocks 0..31: g_base / g_colf (warp-per-output, coalesced);
//     block 32:     g_wfold (coalesced inw column read) + g_cfold.
// =====================================================================
__global__ void prep3_kernel(const float* __restrict__ inw, const float* __restrict__ inb,
                             const float* __restrict__ ow,  const float* __restrict__ ob)
{
    if (blockIdx.x < 32) {
        const int tt   = blockIdx.x * 8 + (threadIdx.x >> 5);  // 0..255
        const int lane = threadIdx.x & 31;
        const int c0   = lane * 8;                             // 8 cols per lane, one head
        float pb = 0.f, pc = 0.f;
        #pragma unroll
        for (int i = 0; i < 2; i++) {
            float4 o4  = *(const float4*)(ow + (size_t)tt * H + c0 + i * 4);
            float4 w1  = *(const float4*)(g_v1 + c0 + i * 4);
            float4 w0  = *(const float4*)(g_v0 + c0 + i * 4);
            pb += o4.x * w1.x + o4.y * w1.y + o4.z * w1.z + o4.w * w1.w;
            pc += o4.x * (w0.x - w1.x) + o4.y * (w0.y - w1.y)
                + o4.z * (w0.z - w1.z) + o4.w * (w0.w - w1.w);
        }
        float b = pb;
        #pragma unroll
        for (int o = 16; o >= 1; o >>= 1) b += __shfl_xor_sync(0xffffffffu, b, o);
        float cv = pc;   // reduce within 8-lane group (one head)
        #pragma unroll
        for (int o = 4; o >= 1; o >>= 1) cv += __shfl_xor_sync(0xffffffffu, cv, o);
        if (lane == 0) g_base[tt] = b + ob[tt];
        if ((lane & 7) == 0) g_colf[lane >> 3][tt] = cv;
    } else {
        const int t = threadIdx.x;
        const float scale = rsqrtf((float)HD);
        float acc[NH] = {0.f, 0.f, 0.f, 0.f};
        #pragma unroll 8
        for (int row = 0; row < H; row++) {
            float dk = (g_k0[row] - g_k1[row]) * scale;
            acc[row >> 6] = fmaf(dk, inw[(size_t)row * H + t], acc[row >> 6]);
        }
        #pragma unroll
        for (int h = 0; h < NH; h++) g_wfold[h][t] = acc[h];
        if (t < NH) {
            float a = 0.f;
            for (int d = 0; d < HD; d++)
                a = fmaf((g_k0[t * HD + d] - g_k1[t * HD + d]) * scale, inb[t * HD + d], a);
            g_cfold[t] = a;
        }
    }
}

// =====================================================================
// Prepack: Wl -> (hi, lo) bf16 split, once per launch.
// =====================================================================
__global__ void prepack_kernel(const float* __restrict__ Wl)
{
    int i = blockIdx.x * blockDim.x + threadIdx.x;
    if (i < H * DIN) {
        uint32_t u  = __float_as_uint(Wl[i]);
        uint32_t hi = u & 0xFFFF0000u;
        float r = __uint_as_float(u) - __uint_as_float(hi);
        g_WlHi[i] = (unsigned short)(hi >> 16);
        g_WlLo[i] = (unsigned short)(__float_as_uint(r) >> 16);
    }
}

// ---------------- helpers ----------------
__device__ __forceinline__ uint32_t smem_u32(const void* p) {
    uint32_t a;
    asm("{ .reg .u64 t; cvta.to.shared.u64 t, %1; cvt.u32.u64 %0, t; }" : "=r"(a) : "l"(p));
    return a;
}
__device__ __forceinline__ void cp16(uint32_t dst, const void* src) {
    asm volatile("cp.async.cg.shared.global [%0], [%1], 16;" :: "r"(dst), "l"(src));
}
__device__ __forceinline__ void cp_commit() { asm volatile("cp.async.commit_group;"); }
template <int N> __device__ __forceinline__ void cp_wait() {
    asm volatile("cp.async.wait_group %0;" :: "n"(N));
}
__device__ __forceinline__ uint32_t pack_hi(float2 f) {
    return __byte_perm(__float_as_uint(f.x), __float_as_uint(f.y), 0x7632);
}
__device__ __forceinline__ uint32_t pack_lo(float2 f) {
    float hx = __uint_as_float(__float_as_uint(f.x) & 0xFFFF0000u);
    float hy = __uint_as_float(__float_as_uint(f.y) & 0xFFFF0000u);
    return __byte_perm(__float_as_uint(f.x - hx), __float_as_uint(f.y - hy), 0x7632);
}
__device__ __forceinline__ void mma16816(float* d, uint32_t a0, uint32_t a1,
                                         uint32_t a2, uint32_t a3,
                                         uint32_t b0, uint32_t b1) {
    asm volatile(
        "mma.sync.aligned.m16n8k16.row.col.f32.bf16.bf16.f32 "
        "{%0,%1,%2,%3}, {%4,%5,%6,%7}, {%8,%9}, {%0,%1,%2,%3};"
        : "+f"(d[0]), "+f"(d[1]), "+f"(d[2]), "+f"(d[3])
        : "r"(a0), "r"(a1), "r"(a2), "r"(a3), "r"(b0), "r"(b1));
}

// =====================================================================
// Main: 128x256 tile of l = X@Wl^T + bl via mma.sync bf16 3-term split.
// (unchanged from the passing R5 kernel)
// =====================================================================
__global__ __launch_bounds__(NTH, 1)
void main_kernel(const float* __restrict__ X,  const float* __restrict__ bl,
                 const float* __restrict__ Wo, const float* __restrict__ bo,
                 float* __restrict__ out, int M)
{
    extern __shared__ char smc[];
    float* smf = (float*)smc;
    const uint32_t sb = smem_u32(smc);
    const int t    = threadIdx.x;
    const int wid  = t >> 5;
    const int lane = t & 31;
    const int q    = lane & 3;
    const int g8   = lane >> 2;
    const int wm   = wid & 3;
    const int wn   = wid >> 2;
    const size_t row0 = (size_t)blockIdx.x * BM;

    float acc[2][8][4];
    #pragma unroll
    for (int nt = 0; nt < 8; nt++) {
        int c0 = wn * 64 + nt * 8 + 2 * q;
        float b0 = __ldg(bl + c0), b1 = __ldg(bl + c0 + 1);
        #pragma unroll
        for (int mt = 0; mt < 2; mt++) {
            acc[mt][nt][0] = b0; acc[mt][nt][1] = b1;
            acc[mt][nt][2] = b0; acc[mt][nt][3] = b1;
        }
    }

    auto load_tiles = [&](int c, int buf) {
        #pragma unroll
        for (int i = 0; i < 2; i++) {
            int id = t + NTH * i;
            int r = id >> 3, cq = id & 7;
            size_t gr = row0 + r; if (gr >= (size_t)M) gr = (size_t)M - 1;
            uint32_t dst = sb + (uint32_t)(buf * A_BYTES + (r * ASTR + cq * 4) * 4);
            cp16(dst, X + gr * DIN + c * BK + cq * 4);
        }
        #pragma unroll
        for (int i = 0; i < 2; i++) {
            int id = t + NTH * i;
            int r = id >> 2, cq = id & 3;
            size_t srco = (size_t)r * DIN + c * BK + cq * 8;
            uint32_t doff = (uint32_t)(buf * B_BYTES + (r * BSTR + cq * 8) * 2);
            cp16(sb + BH_OFF + doff, g_WlHi + srco);
            cp16(sb + BL_OFF + doff, g_WlLo + srco);
        }
    };

    load_tiles(0, 0);
    cp_commit();

    const int ra_base = wm * 32;
    const int nb_base = wn * 64;

    for (int c = 0; c < NKC; c++) {
        if (c + 1 < NKC) { load_tiles(c + 1, (c + 1) & 1); cp_commit(); cp_wait<1>(); }
        else            { cp_wait<0>(); }
        __syncthreads();

        const float* smA = (const float*)(smc + (c & 1) * A_BYTES);
        const char*  sBh = smc + BH_OFF + (c & 1) * B_BYTES;
        const char*  sBl = smc + BL_OFF + (c & 1) * B_BYTES;

        #pragma unroll
        for (int ks = 0; ks < 2; ks++) {
            const int kk = ks * 16 + 2 * q;
            uint32_t Ah[2][4], Al[2][4];
            #pragma unroll
            for (int mt = 0; mt < 2; mt++) {
                int ra = ra_base + mt * 16 + g8;
                float2 f0 = *(const float2*)&smA[ ra      * ASTR + kk    ];
                float2 f1 = *(const float2*)&smA[(ra + 8) * ASTR + kk    ];
                float2 f2 = *(const float2*)&smA[ ra      * ASTR + kk + 8];
                float2 f3 = *(const float2*)&smA[(ra + 8) * ASTR + kk + 8];
                Ah[mt][0] = pack_hi(f0); Ah[mt][1] = pack_hi(f1);
                Ah[mt][2] = pack_hi(f2); Ah[mt][3] = pack_hi(f3);
                Al[mt][0] = pack_lo(f0); Al[mt][1] = pack_lo(f1);
                Al[mt][2] = pack_lo(f2); Al[mt][3] = pack_lo(f3);
            }
            #pragma unroll
            for (int nt = 0; nt < 8; nt++) {
                int nb = nb_base + nt * 8 + g8;
                uint32_t bh0 = *(const uint32_t*)(sBh + (nb * BSTR + kk) * 2);
                uint32_t bh1 = *(const uint32_t*)(sBh + (nb * BSTR + kk + 8) * 2);
                uint32_t bL0 = *(const uint32_t*)(sBl + (nb * BSTR + kk) * 2);
                uint32_t bL1 = *(const uint32_t*)(sBl + (nb * BSTR + kk + 8) * 2);
                #pragma unroll
                for (int mt = 0; mt < 2; mt++) {
                    mma16816(acc[mt][nt], Ah[mt][0], Ah[mt][1], Ah[mt][2], Ah[mt][3], bh0, bh1);
                    mma16816(acc[mt][nt], Al[mt][0], Al[mt][1], Al[mt][2], Al[mt][3], bh0, bh1);
                    mma16816(acc[mt][nt], Ah[mt][0], Ah[mt][1], Ah[mt][2], Ah[mt][3], bL0, bL1);
                }
            }
        }
        __syncthreads();
    }

    float* s_l = smf;
    #pragma unroll
    for (int mt = 0; mt < 2; mt++) {
        int r = wm * 32 + mt * 16 + g8;
        #pragma unroll
        for (int nt = 0; nt < 8; nt++) {
            int cc = wn * 64 + nt * 8 + 2 * q;
            s_l[ r      * SL_STR + cc    ] = acc[mt][nt][0];
            s_l[ r      * SL_STR + cc + 1] = acc[mt][nt][1];
            s_l[(r + 8) * SL_STR + cc    ] = acc[mt][nt][2];
            s_l[(r + 8) * SL_STR + cc + 1] = acc[mt][nt][3];
        }
    }
    __syncthreads();

    {
        const int row  = t >> 2;
        const int part = t & 3;
        const float* lrow = s_l + row * SL_STR;

        float s0 = 0.f, s1 = 0.f, s2 = 0.f, s3 = 0.f, pl = 0.f;
        #pragma unroll 4
        for (int j = 0; j < 64; j++) {
            int col = part * 64 + j;
            float lv = lrow[col];
            s0 = fmaf(g_wfold[0][col], lv, s0);
            s1 = fmaf(g_wfold[1][col], lv, s1);
            s2 = fmaf(g_wfold[2][col], lv, s2);
            s3 = fmaf(g_wfold[3][col], lv, s3);
            pl = fmaf(fmaxf(lv, 0.f), __ldg(Wo + H + col), pl);
        }
        #pragma unroll
        for (int off = 1; off <= 2; off <<= 1) {
            s0 += __shfl_xor_sync(0xffffffffu, s0, off);
            s1 += __shfl_xor_sync(0xffffffffu, s1, off);
            s2 += __shfl_xor_sync(0xffffffffu, s2, off);
            s3 += __shfl_xor_sync(0xffffffffu, s3, off);
        }
        float a00 = 1.f / (1.f + __expf(-(s0 + g_cfold[0])));
        float a01 = 1.f / (1.f + __expf(-(s1 + g_cfold[1])));
        float a02 = 1.f / (1.f + __expf(-(s2 + g_cfold[2])));
        float a03 = 1.f / (1.f + __expf(-(s3 + g_cfold[3])));

        float pat = 0.f;
        #pragma unroll 4
        for (int j = 0; j < 64; j++) {
            int col = part * 64 + j;
            float att = g_base[col];
            att = fmaf(a00, g_colf[0][col], att);
            att = fmaf(a01, g_colf[1][col], att);
            att = fmaf(a02, g_colf[2][col], att);
            att = fmaf(a03, g_colf[3][col], att);
            pat = fmaf(fmaxf(att, 0.f), __ldg(Wo + col), pat);
        }
        float tot = pat + pl;
        #pragma unroll
        for (int off = 1; off <= 2; off <<= 1)
            tot += __shfl_xor_sync(0xffffffffu, tot, off);

        size_t grow = row0 + row;
        if (part == 0 && grow < (size_t)M) out[grow] = tot + __ldg(bo);
    }
}

// =====================================================================
extern "C" void kernel_launch(void* const* d_in, const int* in_sizes, int n_in,
                              void* d_out, int out_size)
{
    const float* user  = (const float*)d_in[0];
    const float* query = (const float*)d_in[1];
    const float* llm   = (const float*)d_in[2];
    const float* Wu    = (const float*)d_in[3];
    const float* bu    = (const float*)d_in[4];
    const float* Wq    = (const float*)d_in[5];
    const float* bq    = (const float*)d_in[6];
    const float* Wl    = (const float*)d_in[7];
    const float* bl    = (const float*)d_in[8];
    const float* inw   = (const float*)d_in[9];
    const float* inb   = (const float*)d_in[10];
    const float* ow    = (const float*)d_in[11];
    const float* ob    = (const float*)d_in[12];
    const float* Wo    = (const float*)d_in[13];
    const float* bo    = (const float*)d_in[14];

    const int M = in_sizes[2] / DIN;

    cudaFuncSetAttribute(main_kernel, cudaFuncAttributeMaxDynamicSharedMemorySize, SMEM_BYTES);

    prep1_kernel<<<64, 256>>>(user, query, Wu, bu, Wq, bq);
    prep2_kernel<<<32, 256>>>(inw, inb);
    prep3_kernel<<<33, 256>>>(inw, inb, ow, ob);
    prepack_kernel<<<(H * DIN + 511) / 512, 512>>>(Wl);
    main_kernel<<<(M + BM - 1) / BM, NTH, SMEM_BYTES>>>(llm, bl, Wo, bo, (float*)d_out, M);
}